// round 7
// baseline (speedup 1.0000x reference)
#include <cuda_runtime.h>

// ParallelBellowsLayers, fully fused single kernel.
// out[b,c] = relu( sum_e relu(x[b,c]*w1[c,e]+b1[c,e]) * w2[c,e] + b2[c] ),
// C=40000, B=128, E=16. Output (B,2,20000) == (B,C) row-major -> elementwise.
//
// b1[c,:]==0 (this dataset) => sum_e relu(x*w1e)*w2e == x * (x>0 ? s_pos : s_neg).
// One block owns 128 channels x ALL 128 rows: params computed once into smem
// (no precompute kernel, no global param round-trip), then a coalesced
// streaming apply phase. evict_last cache policy keeps x/out/weights
// L2-resident across graph replays (R6 measured ~1.1us from this).
// Channels with nonzero b1 / non-finite sums are NaN-flagged and take an
// exact per-element fallback (never taken on this dataset).

#define NGENES 20000
#define NTECH  2
#define CC     (NGENES * NTECH)    // 40000 channels
#define BB     128                 // batch rows
#define EE     16
#define NG     (CC / 4)            // 10000 float4 channel-groups
#define GRPB   32                  // groups per block
#define CHB    (GRPB * 4)          // 128 channels per block
#define NTHR   256
#define SLICES 8                   // row slices (one per warp)
#define RPS    (BB / SLICES)       // 16 rows per thread
#define RB     8                   // row batch (loads in flight)

// ---- L2 evict_last cache-policy memory ops ---------------------------------
__device__ __forceinline__ unsigned long long mk_policy()
{
    unsigned long long pol;
    asm volatile("createpolicy.fractional.L2::evict_last.b64 %0, 1.0;" : "=l"(pol));
    return pol;
}
__device__ __forceinline__ float4 ldg_el(const float* p, unsigned long long pol)
{
    float4 v;
    asm volatile("ld.global.nc.L2::cache_hint.v4.f32 {%0,%1,%2,%3}, [%4], %5;"
                 : "=f"(v.x), "=f"(v.y), "=f"(v.z), "=f"(v.w)
                 : "l"(p), "l"(pol));
    return v;
}
__device__ __forceinline__ float ldg_el1(const float* p, unsigned long long pol)
{
    float v;
    asm volatile("ld.global.nc.L2::cache_hint.f32 %0, [%1], %2;"
                 : "=f"(v) : "l"(p), "l"(pol));
    return v;
}
__device__ __forceinline__ void stg_el(float* p, float4 v, unsigned long long pol)
{
    asm volatile("st.global.L2::cache_hint.v4.f32 [%0], {%1,%2,%3,%4}, %5;"
                 :: "l"(p), "f"(v.x), "f"(v.y), "f"(v.z), "f"(v.w), "l"(pol)
                 : "memory");
}
// -----------------------------------------------------------------------------

// Exact per-element path for flagged channels (never taken on this dataset).
__device__ __noinline__ float bellows_exact(float xv, int c,
                                            const float* __restrict__ w1,
                                            const float* __restrict__ b1,
                                            const float* __restrict__ w2,
                                            float bias)
{
    float acc = 0.f;
    const float* w1r = w1 + (size_t)c * EE;
    const float* b1r = b1 + (size_t)c * EE;
    const float* w2r = w2 + (size_t)c * EE;
#pragma unroll 4
    for (int e = 0; e < EE; ++e) {
        float h = fmaxf(fmaf(xv, w1r[e], b1r[e]), 0.f);
        acc = fmaf(h, w2r[e], acc);
    }
    return fmaxf(acc + bias, 0.f);
}

__device__ __forceinline__ float bellows_fast(float xv, float sp, float sn, float bias)
{
    float s = (xv > 0.f) ? sp : sn;
    return fmaxf(fmaf(xv, s, bias), 0.f);
}

__device__ __forceinline__ void slice_acc(float4 a, float4 z, float4 w,
                                          float& sp, float& sn, bool& ok)
{
    ok = ok && (z.x == 0.f) && (z.y == 0.f) && (z.z == 0.f) && (z.w == 0.f);
    float p;
    p = a.x * w.x; sp += (a.x > 0.f) ? p : 0.f; sn += (a.x < 0.f) ? p : 0.f;
    p = a.y * w.y; sp += (a.y > 0.f) ? p : 0.f; sn += (a.y < 0.f) ? p : 0.f;
    p = a.z * w.z; sp += (a.z > 0.f) ? p : 0.f; sn += (a.z < 0.f) ? p : 0.f;
    p = a.w * w.w; sp += (a.w > 0.f) ? p : 0.f; sn += (a.w < 0.f) ? p : 0.f;
}

__global__ void __launch_bounds__(NTHR)
fused_kernel(const float* __restrict__ x,
             const float* __restrict__ w1,
             const float* __restrict__ b1,
             const float* __restrict__ w2,
             const float* __restrict__ b2,
             float* __restrict__ out)
{
    __shared__ float4 s_sp[GRPB];
    __shared__ float4 s_sn[GRPB];
    __shared__ float4 s_bf[GRPB];

    const int tid = threadIdx.x;
    unsigned long long pol = mk_policy();

    // ---- Phase 1: per-channel params into smem (2 threads per channel) ----
    {
        int chl  = tid >> 1;            // local channel 0..127
        int half = tid & 1;             // E-half: [0,8) or [8,16)
        int c    = blockIdx.x * CHB + chl;

        float sp = 0.f, sn = 0.f;
        bool ok = true;
        if (c < CC) {
            size_t off = (size_t)c * EE + half * 8;
            float4 a0 = ldg_el(w1 + off, pol);
            float4 a1 = ldg_el(w1 + off + 4, pol);
            float4 z0 = ldg_el(b1 + off, pol);
            float4 z1 = ldg_el(b1 + off + 4, pol);
            float4 w0 = ldg_el(w2 + off, pol);
            float4 w1v = ldg_el(w2 + off + 4, pol);
            slice_acc(a0, z0, w0, sp, sn, ok);
            slice_acc(a1, z1, w1v, sp, sn, ok);
        }
        if (!ok) sp = __int_as_float(0x7fc00000);  // NaN survives the reduction

        sp += __shfl_xor_sync(0xffffffffu, sp, 1);
        sn += __shfl_xor_sync(0xffffffffu, sn, 1);

        if (half == 0) {
            if (!isfinite(sp) || !isfinite(sn)) sp = __int_as_float(0x7fc00000);
            float bfv = (c < CC) ? ldg_el1(b2 + c, pol) : 0.f;
            reinterpret_cast<float*>(s_sp)[chl] = sp;
            reinterpret_cast<float*>(s_sn)[chl] = sn;
            reinterpret_cast<float*>(s_bf)[chl] = bfv;
        }
    }
    __syncthreads();

    // ---- Phase 2: streaming apply, warp-coalesced ----
    const int grp   = tid & 31;         // channel-group within block
    const int slice = tid >> 5;         // row slice (== warp id)
    const int g     = blockIdx.x * GRPB + grp;
    if (g >= NG) return;
    const int c0 = g * 4;

    float4 sp4 = s_sp[grp];
    float4 sn4 = s_sn[grp];
    float4 bf4 = s_bf[grp];

    bool any_fb = (sp4.x != sp4.x) || (sp4.y != sp4.y) ||
                  (sp4.z != sp4.z) || (sp4.w != sp4.w);

    const int row0 = slice * RPS;
    const float* xp = x   + (size_t)row0 * CC + c0;
    float*       op = out + (size_t)row0 * CC + c0;

    if (!any_fb) {
#pragma unroll
        for (int it = 0; it < RPS / RB; ++it) {
            float4 xv[RB];
#pragma unroll
            for (int r = 0; r < RB; ++r)
                xv[r] = ldg_el(xp + (size_t)(it * RB + r) * CC, pol);
#pragma unroll
            for (int r = 0; r < RB; ++r) {
                float4 o;
                o.x = bellows_fast(xv[r].x, sp4.x, sn4.x, bf4.x);
                o.y = bellows_fast(xv[r].y, sp4.y, sn4.y, bf4.y);
                o.z = bellows_fast(xv[r].z, sp4.z, sn4.z, bf4.z);
                o.w = bellows_fast(xv[r].w, sp4.w, sn4.w, bf4.w);
                stg_el(op + (size_t)(it * RB + r) * CC, o, pol);
            }
        }
    } else {
#pragma unroll 2
        for (int r = 0; r < RPS; ++r) {
            float4 xv = ldg_el(xp + (size_t)r * CC, pol);
            float4 o;
            o.x = (sp4.x != sp4.x) ? bellows_exact(xv.x, c0 + 0, w1, b1, w2, bf4.x)
                                   : bellows_fast(xv.x, sp4.x, sn4.x, bf4.x);
            o.y = (sp4.y != sp4.y) ? bellows_exact(xv.y, c0 + 1, w1, b1, w2, bf4.y)
                                   : bellows_fast(xv.y, sp4.y, sn4.y, bf4.y);
            o.z = (sp4.z != sp4.z) ? bellows_exact(xv.z, c0 + 2, w1, b1, w2, bf4.z)
                                   : bellows_fast(xv.z, sp4.z, sn4.z, bf4.z);
            o.w = (sp4.w != sp4.w) ? bellows_exact(xv.w, c0 + 3, w1, b1, w2, bf4.w)
                                   : bellows_fast(xv.w, sp4.w, sn4.w, bf4.w);
            stg_el(op + (size_t)r * CC, o, pol);
        }
    }
}

extern "C" void kernel_launch(void* const* d_in, const int* in_sizes, int n_in,
                              void* d_out, int out_size)
{
    const float* x  = (const float*)d_in[0];   // (128, 40000)
    const float* w1 = (const float*)d_in[1];   // (40000, 16)
    const float* b1 = (const float*)d_in[2];   // (40000, 16)
    const float* w2 = (const float*)d_in[3];   // (40000, 16)
    const float* b2 = (const float*)d_in[4];   // (40000,)
    float* out = (float*)d_out;                // (128, 2, 20000) == (128, 40000)

    int nblocks = (NG + GRPB - 1) / GRPB;      // 313
    fused_kernel<<<nblocks, NTHR>>>(x, w1, b1, w2, b2, out);
}

// round 8
// speedup vs baseline: 1.0029x; 1.0029x over previous
#include <cuda_runtime.h>

// ParallelBellowsLayers, fused single kernel, batch-split for occupancy.
// out[b,c] = relu( sum_e relu(x[b,c]*w1[c,e]+b1[c,e]) * w2[c,e] + b2[c] ),
// C=40000, B=128, E=16. Output (B,2,20000) == (B,C) row-major -> elementwise.
//
// b1[c,:]==0 (this dataset) => sum_e relu(x*w1e)*w2e == x * (x>0 ? s_pos : s_neg).
// R7 post-mortem: fusing into one 313-block kernel dropped occupancy to 24%
// and gave back exactly what the removed launch saved. This version keeps the
// single node but splits rows 2-ways: grid (313, 2) = 626 blocks (~50% occ),
// each block recomputes its 128 channels' params into smem (weights read 2x
// total -- cheap, L2-resident) then streams 64 rows.
// evict_last cache policy pins x/out/weights in L2 across graph replays.
// Channels with nonzero b1 / non-finite sums are NaN-flagged and take an
// exact per-element fallback (never taken on this dataset).

#define NGENES 20000
#define NTECH  2
#define CC     (NGENES * NTECH)    // 40000 channels
#define BB     128                 // batch rows
#define EE     16
#define NG     (CC / 4)            // 10000 float4 channel-groups
#define GRPB   32                  // groups per block
#define CHB    (GRPB * 4)          // 128 channels per block
#define NTHR   256
#define RSPLIT 2                   // row split across blockIdx.y
#define ROWSB  (BB / RSPLIT)       // 64 rows per block
#define SLICES 8                   // row slices (one per warp)
#define RPS    (ROWSB / SLICES)    // 8 rows per thread
#define RB     4                   // row batch (loads in flight per batch)

// ---- L2 evict_last cache-policy memory ops ---------------------------------
__device__ __forceinline__ unsigned long long mk_policy()
{
    unsigned long long pol;
    asm volatile("createpolicy.fractional.L2::evict_last.b64 %0, 1.0;" : "=l"(pol));
    return pol;
}
__device__ __forceinline__ float4 ldg_el(const float* p, unsigned long long pol)
{
    float4 v;
    asm volatile("ld.global.nc.L2::cache_hint.v4.f32 {%0,%1,%2,%3}, [%4], %5;"
                 : "=f"(v.x), "=f"(v.y), "=f"(v.z), "=f"(v.w)
                 : "l"(p), "l"(pol));
    return v;
}
__device__ __forceinline__ float ldg_el1(const float* p, unsigned long long pol)
{
    float v;
    asm volatile("ld.global.nc.L2::cache_hint.f32 %0, [%1], %2;"
                 : "=f"(v) : "l"(p), "l"(pol));
    return v;
}
__device__ __forceinline__ void stg_el(float* p, float4 v, unsigned long long pol)
{
    asm volatile("st.global.L2::cache_hint.v4.f32 [%0], {%1,%2,%3,%4}, %5;"
                 :: "l"(p), "f"(v.x), "f"(v.y), "f"(v.z), "f"(v.w), "l"(pol)
                 : "memory");
}
// -----------------------------------------------------------------------------

// Exact per-element path for flagged channels (never taken on this dataset).
__device__ __noinline__ float bellows_exact(float xv, int c,
                                            const float* __restrict__ w1,
                                            const float* __restrict__ b1,
                                            const float* __restrict__ w2,
                                            float bias)
{
    float acc = 0.f;
    const float* w1r = w1 + (size_t)c * EE;
    const float* b1r = b1 + (size_t)c * EE;
    const float* w2r = w2 + (size_t)c * EE;
#pragma unroll 4
    for (int e = 0; e < EE; ++e) {
        float h = fmaxf(fmaf(xv, w1r[e], b1r[e]), 0.f);
        acc = fmaf(h, w2r[e], acc);
    }
    return fmaxf(acc + bias, 0.f);
}

__device__ __forceinline__ float bellows_fast(float xv, float sp, float sn, float bias)
{
    float s = (xv > 0.f) ? sp : sn;
    return fmaxf(fmaf(xv, s, bias), 0.f);
}

__device__ __forceinline__ void slice_acc(float4 a, float4 z, float4 w,
                                          float& sp, float& sn, bool& ok)
{
    ok = ok && (z.x == 0.f) && (z.y == 0.f) && (z.z == 0.f) && (z.w == 0.f);
    float p;
    p = a.x * w.x; sp += (a.x > 0.f) ? p : 0.f; sn += (a.x < 0.f) ? p : 0.f;
    p = a.y * w.y; sp += (a.y > 0.f) ? p : 0.f; sn += (a.y < 0.f) ? p : 0.f;
    p = a.z * w.z; sp += (a.z > 0.f) ? p : 0.f; sn += (a.z < 0.f) ? p : 0.f;
    p = a.w * w.w; sp += (a.w > 0.f) ? p : 0.f; sn += (a.w < 0.f) ? p : 0.f;
}

__global__ void __launch_bounds__(NTHR)
fused_kernel(const float* __restrict__ x,
             const float* __restrict__ w1,
             const float* __restrict__ b1,
             const float* __restrict__ w2,
             const float* __restrict__ b2,
             float* __restrict__ out)
{
    __shared__ float4 s_sp[GRPB];
    __shared__ float4 s_sn[GRPB];
    __shared__ float4 s_bf[GRPB];

    const int tid = threadIdx.x;
    unsigned long long pol = mk_policy();

    // ---- Phase 1: per-channel params into smem (2 threads per channel) ----
    {
        int chl  = tid >> 1;            // local channel 0..127
        int half = tid & 1;             // E-half: [0,8) or [8,16)
        int c    = blockIdx.x * CHB + chl;

        float sp = 0.f, sn = 0.f;
        bool ok = true;
        if (c < CC) {
            size_t off = (size_t)c * EE + half * 8;
            float4 a0 = ldg_el(w1 + off, pol);
            float4 a1 = ldg_el(w1 + off + 4, pol);
            float4 z0 = ldg_el(b1 + off, pol);
            float4 z1 = ldg_el(b1 + off + 4, pol);
            float4 w0 = ldg_el(w2 + off, pol);
            float4 w1v = ldg_el(w2 + off + 4, pol);
            slice_acc(a0, z0, w0, sp, sn, ok);
            slice_acc(a1, z1, w1v, sp, sn, ok);
        }
        if (!ok) sp = __int_as_float(0x7fc00000);  // NaN survives the reduction

        sp += __shfl_xor_sync(0xffffffffu, sp, 1);
        sn += __shfl_xor_sync(0xffffffffu, sn, 1);

        if (half == 0) {
            if (!isfinite(sp) || !isfinite(sn)) sp = __int_as_float(0x7fc00000);
            float bfv = (c < CC) ? ldg_el1(b2 + c, pol) : 0.f;
            reinterpret_cast<float*>(s_sp)[chl] = sp;
            reinterpret_cast<float*>(s_sn)[chl] = sn;
            reinterpret_cast<float*>(s_bf)[chl] = bfv;
        }
    }
    __syncthreads();

    // ---- Phase 2: streaming apply, warp-coalesced, 8 rows/thread ----
    const int grp   = tid & 31;         // channel-group within block
    const int slice = tid >> 5;         // row slice (== warp id)
    const int g     = blockIdx.x * GRPB + grp;
    if (g >= NG) return;
    const int c0 = g * 4;

    float4 sp4 = s_sp[grp];
    float4 sn4 = s_sn[grp];
    float4 bf4 = s_bf[grp];

    bool any_fb = (sp4.x != sp4.x) || (sp4.y != sp4.y) ||
                  (sp4.z != sp4.z) || (sp4.w != sp4.w);

    const int row0 = blockIdx.y * ROWSB + slice * RPS;
    const float* xp = x   + (size_t)row0 * CC + c0;
    float*       op = out + (size_t)row0 * CC + c0;

    if (!any_fb) {
#pragma unroll
        for (int it = 0; it < RPS / RB; ++it) {
            float4 xv[RB];
#pragma unroll
            for (int r = 0; r < RB; ++r)
                xv[r] = ldg_el(xp + (size_t)(it * RB + r) * CC, pol);
#pragma unroll
            for (int r = 0; r < RB; ++r) {
                float4 o;
                o.x = bellows_fast(xv[r].x, sp4.x, sn4.x, bf4.x);
                o.y = bellows_fast(xv[r].y, sp4.y, sn4.y, bf4.y);
                o.z = bellows_fast(xv[r].z, sp4.z, sn4.z, bf4.z);
                o.w = bellows_fast(xv[r].w, sp4.w, sn4.w, bf4.w);
                stg_el(op + (size_t)(it * RB + r) * CC, o, pol);
            }
        }
    } else {
#pragma unroll 2
        for (int r = 0; r < RPS; ++r) {
            float4 xv = ldg_el(xp + (size_t)r * CC, pol);
            float4 o;
            o.x = (sp4.x != sp4.x) ? bellows_exact(xv.x, c0 + 0, w1, b1, w2, bf4.x)
                                   : bellows_fast(xv.x, sp4.x, sn4.x, bf4.x);
            o.y = (sp4.y != sp4.y) ? bellows_exact(xv.y, c0 + 1, w1, b1, w2, bf4.y)
                                   : bellows_fast(xv.y, sp4.y, sn4.y, bf4.y);
            o.z = (sp4.z != sp4.z) ? bellows_exact(xv.z, c0 + 2, w1, b1, w2, bf4.z)
                                   : bellows_fast(xv.z, sp4.z, sn4.z, bf4.z);
            o.w = (sp4.w != sp4.w) ? bellows_exact(xv.w, c0 + 3, w1, b1, w2, bf4.w)
                                   : bellows_fast(xv.w, sp4.w, sn4.w, bf4.w);
            stg_el(op + (size_t)r * CC, o, pol);
        }
    }
}

extern "C" void kernel_launch(void* const* d_in, const int* in_sizes, int n_in,
                              void* d_out, int out_size)
{
    const float* x  = (const float*)d_in[0];   // (128, 40000)
    const float* w1 = (const float*)d_in[1];   // (40000, 16)
    const float* b1 = (const float*)d_in[2];   // (40000, 16)
    const float* w2 = (const float*)d_in[3];   // (40000, 16)
    const float* b2 = (const float*)d_in[4];   // (40000,)
    float* out = (float*)d_out;                // (128, 2, 20000) == (128, 40000)

    dim3 grid((NG + GRPB - 1) / GRPB, RSPLIT); // (313, 2) = 626 blocks
    fused_kernel<<<grid, NTHR>>>(x, w1, b1, w2, b2, out);
}